// round 6
// baseline (speedup 1.0000x reference)
#include <cuda_runtime.h>
#include <math.h>
#include <stdint.h>

#define T_SEQ 2048
#define HID 4096
#define NH 32
#define NKV 8
#define HD 128
#define FSTR 132   // flash smem row stride

// Scratch (allocation-free rule: __device__ globals)
__device__ float g_Q [(size_t)T_SEQ * NH * HD];
__device__ float g_K [(size_t)T_SEQ * NKV * HD];
__device__ float g_VT[(size_t)NKV * HD * T_SEQ];
__device__ float g_O [(size_t)T_SEQ * NH * HD];

__device__ __forceinline__ unsigned f2tf(float f) {
    unsigned u;
    asm("cvt.rna.tf32.f32 %0, %1;" : "=r"(u) : "f"(f));
    return u;
}
__device__ __forceinline__ uint32_t smem_u32(const void* p) {
    uint32_t a;
    asm("{ .reg .u64 t; cvta.to.shared.u64 t, %1; cvt.u32.u64 %0, t; }"
        : "=r"(a) : "l"(p));
    return a;
}

#define MMA_TF32(d, a0,a1,a2,a3, b0,b1)                                       \
    asm volatile(                                                             \
        "mma.sync.aligned.m16n8k8.row.col.f32.tf32.tf32.f32 "                 \
        "{%0,%1,%2,%3}, {%4,%5,%6,%7}, {%8,%9}, {%0,%1,%2,%3};"               \
        : "+f"((d)[0]), "+f"((d)[1]), "+f"((d)[2]), "+f"((d)[3])              \
        : "r"(a0), "r"(a1), "r"(a2), "r"(a3), "r"(b0), "r"(b1))

#define CP_ASYNC16(dst, src) \
    asm volatile("cp.async.cg.shared.global [%0], [%1], 16;" :: "r"(dst), "l"(src))
#define CP_COMMIT()  asm volatile("cp.async.commit_group;" ::: "memory")
#define CP_WAIT2()   asm volatile("cp.async.wait_group 2;" ::: "memory")

// ---------------------------------------------------------------------------
// TF32 GEMM: C[M,N] = A[M,K] * B^T (B stored [N,K] row-major).
// Block tile 128(M) x 256(N), K-chunk 32, 256 threads (8 warps, 2x4, each
// 64x64 via m16n8k8). 3-stage cp.async pipeline; raw fp32 in smem, cvt to
// tf32 in the fragment path. Rows padded to 36 floats (conflict-free).
// Requires M%128==0, N%256==0, K%32==0, K/32 >= 3.
// ---------------------------------------------------------------------------
#define ASTRIDE 36
#define STAGE_FLOATS ((128 + 256) * ASTRIDE)           // 13824 floats
#define STAGE_BYTES  (STAGE_FLOATS * 4)                // 55296 B
#define GEMM_SMEM    (3 * STAGE_BYTES)                 // 165888 B

__device__ __forceinline__ void gemm_tc_core(
    const float* __restrict__ A, const float* __restrict__ B, float* __restrict__ C,
    int K, int lda, int ldb, int ldc, int bm, int bn)
{
    extern __shared__ float smf[];
    const uint32_t smb = smem_u32(smf);

    const int tid  = threadIdx.x;
    const int lane = tid & 31;
    const int w    = tid >> 5;
    const int g    = lane >> 2;
    const int t    = lane & 3;
    const int wm   = (w >> 2) * 64;     // 0 or 64
    const int wn   = (w & 3) * 64;      // 0,64,128,192

    float acc[4][8][4];
    #pragma unroll
    for (int mi = 0; mi < 4; mi++)
        #pragma unroll
        for (int ni = 0; ni < 8; ni++)
            #pragma unroll
            for (int q = 0; q < 4; q++) acc[mi][ni][q] = 0.0f;

    // Fill mapping: 16B chunks; 8 chunks per 32-float row.
    // A tile: 128 rows * 8 = 1024 chunks -> 4 per thread.
    // B tile: 256 rows * 8 = 2048 chunks -> 8 per thread.
    const int ar = tid >> 3;            // 0..31 base row (A: +32*p)
    const int ac = (tid & 7) * 4;       // float offset within row (0,4,..28)
    const float* Ap = A + (size_t)(bm + ar) * lda + ac;
    const float* Bp = B + (size_t)(bn + ar) * ldb + ac;
    const uint32_t aoff = (uint32_t)(ar * ASTRIDE + ac) * 4u;
    const uint32_t boff = (uint32_t)((128 + ar) * ASTRIDE + ac) * 4u;

    const int nch = K >> 5;

    #define FILL(stage, k0) do {                                                  \
        const uint32_t sb = smb + (stage) * STAGE_BYTES;                           \
        _Pragma("unroll")                                                          \
        for (int p = 0; p < 4; p++)                                                \
            CP_ASYNC16(sb + aoff + (uint32_t)(32 * p * ASTRIDE) * 4u,              \
                       Ap + (size_t)(32 * p) * lda + (k0));                        \
        _Pragma("unroll")                                                          \
        for (int p = 0; p < 8; p++)                                                \
            CP_ASYNC16(sb + boff + (uint32_t)(32 * p * ASTRIDE) * 4u,              \
                       Bp + (size_t)(32 * p) * ldb + (k0));                        \
    } while (0)

    FILL(0, 0);  CP_COMMIT();
    FILL(1, 32); CP_COMMIT();
    FILL(2, 64); CP_COMMIT();

    for (int i = 0; i < nch; i++) {
        const int s = i - (i / 3) * 3;  // i % 3
        CP_WAIT2();
        __syncthreads();

        const float* SA = smf + s * STAGE_FLOATS;
        const float* SB = SA + 128 * ASTRIDE;

        #pragma unroll
        for (int ks = 0; ks < 32; ks += 8) {
            unsigned af[4][4], bf[8][2];
            #pragma unroll
            for (int mi = 0; mi < 4; mi++) {
                const int r = wm + mi * 16;
                af[mi][0] = f2tf(SA[(r + g    ) * ASTRIDE + ks + t    ]);
                af[mi][1] = f2tf(SA[(r + g + 8) * ASTRIDE + ks + t    ]);
                af[mi][2] = f2tf(SA[(r + g    ) * ASTRIDE + ks + t + 4]);
                af[mi][3] = f2tf(SA[(r + g + 8) * ASTRIDE + ks + t + 4]);
            }
            #pragma unroll
            for (int ni = 0; ni < 8; ni++) {
                const int cb = wn + ni * 8 + g;
                bf[ni][0] = f2tf(SB[cb * ASTRIDE + ks + t    ]);
                bf[ni][1] = f2tf(SB[cb * ASTRIDE + ks + t + 4]);
            }
            #pragma unroll
            for (int mi = 0; mi < 4; mi++)
                #pragma unroll
                for (int ni = 0; ni < 8; ni++)
                    MMA_TF32(acc[mi][ni], af[mi][0], af[mi][1], af[mi][2], af[mi][3],
                             bf[ni][0], bf[ni][1]);
        }
        __syncthreads();   // done reading stage s before refill

        if (i + 3 < nch) FILL(s, (i + 3) * 32);
        CP_COMMIT();       // keep group count aligned (empty groups complete at once)
    }
    #undef FILL

    // Epilogue
    #pragma unroll
    for (int mi = 0; mi < 4; mi++) {
        const size_t r0 = (size_t)(bm + wm + mi * 16 + g) * ldc + bn + wn;
        const size_t r1 = r0 + (size_t)8 * ldc;
        #pragma unroll
        for (int ni = 0; ni < 8; ni++) {
            const int cc = ni * 8 + 2 * t;
            *reinterpret_cast<float2*>(C + r0 + cc) = make_float2(acc[mi][ni][0], acc[mi][ni][1]);
            *reinterpret_cast<float2*>(C + r1 + cc) = make_float2(acc[mi][ni][2], acc[mi][ni][3]);
        }
    }
}

__global__ __launch_bounds__(256)
void gemm_tc(const float* __restrict__ A, const float* __restrict__ B,
             float* __restrict__ C, int K, int lda, int ldb, int ldc)
{
    gemm_tc_core(A, B, C, K, lda, ldb, ldc, blockIdx.y * 128, blockIdx.x * 256);
}

// Fused K-proj + VT-proj (64 + 64 CTAs in one launch)
__global__ __launch_bounds__(256)
void gemm_tc_kv(const float* __restrict__ x, const float* __restrict__ Wk,
                const float* __restrict__ Wv, float* __restrict__ K, float* __restrict__ VT)
{
    if (blockIdx.y == 0)   // K = x * Wk^T  [2048,1024]: 16(M) x 4(N) tiles
        gemm_tc_core(x, Wk, K, HID, HID, HID, NKV * HD,
                     (blockIdx.x >> 2) * 128, (blockIdx.x & 3) * 256);
    else                   // VT = Wv * x^T [1024,2048]: 8(M) x 8(N) tiles
        gemm_tc_core(Wv, x, VT, HID, HID, HID, T_SEQ,
                     (blockIdx.x >> 3) * 128, (blockIdx.x & 7) * 256);
}

// ---------------------------------------------------------------------------
// Flash attention (unchanged from passing R4)
// ---------------------------------------------------------------------------
__global__ __launch_bounds__(256)
void flash_attn(const float* __restrict__ Qg, const float* __restrict__ Kg,
                const float* __restrict__ VTg, float* __restrict__ Og)
{
    extern __shared__ unsigned sm[];
    unsigned* Qs = sm;
    unsigned* Ks = sm + 128 * FSTR;
    unsigned* Vs = sm + 2 * 128 * FSTR;

    const int h  = blockIdx.y;
    const int ib = gridDim.x - 1 - blockIdx.x;
    const int kv = h >> 2;
    const int tid  = threadIdx.x;
    const int lane = tid & 31;
    const int w    = tid >> 5;
    const int g    = lane >> 2;
    const int t    = lane & 3;
    const int wr   = w * 16;
    const float scale = 0.088388347648318447f;

    #pragma unroll
    for (int p = 0; p < 16; p++) {
        const int fidx = tid + 256 * p;
        const int r = fidx >> 5, c4 = (fidx & 31) * 4;
        float4 q = *reinterpret_cast<const float4*>(
            Qg + (size_t)(ib * 128 + r) * (NH * HD) + h * HD + c4);
        unsigned* d = &Qs[r * FSTR + c4];
        d[0] = f2tf(q.x * scale); d[1] = f2tf(q.y * scale);
        d[2] = f2tf(q.z * scale); d[3] = f2tf(q.w * scale);
    }

    float m0 = -1e30f, m1 = -1e30f, l0 = 0.0f, l1 = 0.0f;
    float o[16][4];
    #pragma unroll
    for (int ni = 0; ni < 16; ni++)
        #pragma unroll
        for (int q = 0; q < 4; q++) o[ni][q] = 0.0f;

    for (int j = 0; j <= ib; j++) {
        __syncthreads();
        #pragma unroll
        for (int p = 0; p < 16; p++) {
            const int fidx = tid + 256 * p;
            const int r = fidx >> 5, c4 = (fidx & 31) * 4;
            float4 kk = *reinterpret_cast<const float4*>(
                Kg + (size_t)(j * 128 + r) * (NKV * HD) + kv * HD + c4);
            unsigned* dk = &Ks[r * FSTR + c4];
            dk[0] = f2tf(kk.x); dk[1] = f2tf(kk.y); dk[2] = f2tf(kk.z); dk[3] = f2tf(kk.w);
            float4 vv = *reinterpret_cast<const float4*>(
                VTg + ((size_t)kv * HD + r) * T_SEQ + j * 128 + c4);
            unsigned* dv = &Vs[r * FSTR + c4];
            dv[0] = f2tf(vv.x); dv[1] = f2tf(vv.y); dv[2] = f2tf(vv.z); dv[3] = f2tf(vv.w);
        }
        __syncthreads();

        float s[16][4];
        #pragma unroll
        for (int ni = 0; ni < 16; ni++)
            #pragma unroll
            for (int q = 0; q < 4; q++) s[ni][q] = 0.0f;

        #pragma unroll
        for (int ks = 0; ks < 16; ks++) {
            const int k8 = ks * 8;
            const unsigned a0 = Qs[(wr + g    ) * FSTR + k8 + t    ];
            const unsigned a1 = Qs[(wr + g + 8) * FSTR + k8 + t    ];
            const unsigned a2 = Qs[(wr + g    ) * FSTR + k8 + t + 4];
            const unsigned a3 = Qs[(wr + g + 8) * FSTR + k8 + t + 4];
            #pragma unroll
            for (int ni = 0; ni < 16; ni++) {
                const unsigned b0 = Ks[(ni * 8 + g) * FSTR + k8 + t    ];
                const unsigned b1 = Ks[(ni * 8 + g) * FSTR + k8 + t + 4];
                MMA_TF32(s[ni], a0, a1, a2, a3, b0, b1);
            }
        }

        if (j == ib) {
            #pragma unroll
            for (int ni = 0; ni < 16; ni++) {
                const int c0 = ni * 8 + 2 * t;
                const int r0 = wr + g, r1 = wr + g + 8;
                if (c0     > r0) s[ni][0] = -1e30f;
                if (c0 + 1 > r0) s[ni][1] = -1e30f;
                if (c0     > r1) s[ni][2] = -1e30f;
                if (c0 + 1 > r1) s[ni][3] = -1e30f;
            }
        }

        float bm0 = -1e30f, bm1 = -1e30f;
        #pragma unroll
        for (int ni = 0; ni < 16; ni++) {
            bm0 = fmaxf(bm0, fmaxf(s[ni][0], s[ni][1]));
            bm1 = fmaxf(bm1, fmaxf(s[ni][2], s[ni][3]));
        }
        bm0 = fmaxf(bm0, __shfl_xor_sync(0xffffffffu, bm0, 1));
        bm0 = fmaxf(bm0, __shfl_xor_sync(0xffffffffu, bm0, 2));
        bm1 = fmaxf(bm1, __shfl_xor_sync(0xffffffffu, bm1, 1));
        bm1 = fmaxf(bm1, __shfl_xor_sync(0xffffffffu, bm1, 2));

        const float mn0 = fmaxf(m0, bm0), mn1 = fmaxf(m1, bm1);
        const float al0 = __expf(m0 - mn0), al1 = __expf(m1 - mn1);
        m0 = mn0; m1 = mn1;

        float rs0 = 0.0f, rs1 = 0.0f;
        #pragma unroll
        for (int ni = 0; ni < 16; ni++) {
            s[ni][0] = __expf(s[ni][0] - mn0);
            s[ni][1] = __expf(s[ni][1] - mn0);
            s[ni][2] = __expf(s[ni][2] - mn1);
            s[ni][3] = __expf(s[ni][3] - mn1);
            rs0 += s[ni][0] + s[ni][1];
            rs1 += s[ni][2] + s[ni][3];
        }
        rs0 += __shfl_xor_sync(0xffffffffu, rs0, 1);
        rs0 += __shfl_xor_sync(0xffffffffu, rs0, 2);
        rs1 += __shfl_xor_sync(0xffffffffu, rs1, 1);
        rs1 += __shfl_xor_sync(0xffffffffu, rs1, 2);
        l0 = l0 * al0 + rs0;
        l1 = l1 * al1 + rs1;

        #pragma unroll
        for (int ni = 0; ni < 16; ni++) {
            o[ni][0] *= al0; o[ni][1] *= al0;
            o[ni][2] *= al1; o[ni][3] *= al1;
        }

        #pragma unroll
        for (int ni = 0; ni < 16; ni++)
            #pragma unroll
            for (int q = 0; q < 4; q++)
                s[ni][q] = __uint_as_float(f2tf(s[ni][q]));

        const int base = (lane & ~3) | (t >> 1);
        const bool odd = (t & 1);
        #pragma unroll
        for (int kt = 0; kt < 16; kt++) {
            const float v0 = __shfl_sync(0xffffffffu, s[kt][0], base);
            const float v1 = __shfl_sync(0xffffffffu, s[kt][1], base);
            const float v2 = __shfl_sync(0xffffffffu, s[kt][2], base);
            const float v3 = __shfl_sync(0xffffffffu, s[kt][3], base);
            const float u0 = __shfl_sync(0xffffffffu, s[kt][0], base + 2);
            const float u1 = __shfl_sync(0xffffffffu, s[kt][1], base + 2);
            const float u2 = __shfl_sync(0xffffffffu, s[kt][2], base + 2);
            const float u3 = __shfl_sync(0xffffffffu, s[kt][3], base + 2);
            const unsigned a0 = __float_as_uint(odd ? v1 : v0);
            const unsigned a1 = __float_as_uint(odd ? v3 : v2);
            const unsigned a2 = __float_as_uint(odd ? u1 : u0);
            const unsigned a3 = __float_as_uint(odd ? u3 : u2);
            const int k8 = kt * 8;
            #pragma unroll
            for (int ni = 0; ni < 16; ni++) {
                const unsigned b0 = Vs[(ni * 8 + g) * FSTR + k8 + t    ];
                const unsigned b1 = Vs[(ni * 8 + g) * FSTR + k8 + t + 4];
                MMA_TF32(o[ni], a0, a1, a2, a3, b0, b1);
            }
        }
    }

    const float i0 = 1.0f / l0, i1 = 1.0f / l1;
    const size_t r0 = (size_t)(ib * 128 + wr + g) * (NH * HD) + h * HD;
    const size_t r1 = r0 + (size_t)8 * (NH * HD);
    #pragma unroll
    for (int ni = 0; ni < 16; ni++) {
        const int cc = ni * 8 + 2 * t;
        *reinterpret_cast<float2*>(Og + r0 + cc) = make_float2(o[ni][0] * i0, o[ni][1] * i0);
        *reinterpret_cast<float2*>(Og + r1 + cc) = make_float2(o[ni][2] * i1, o[ni][3] * i1);
    }
}

// ---------------------------------------------------------------------------
// Llama-3 RoPE (unchanged)
// ---------------------------------------------------------------------------
__global__ void rope_kernel(float* __restrict__ q, int heads)
{
    const int t = blockIdx.x;
    const int h = blockIdx.y * 4 + threadIdx.y;
    const int i = threadIdx.x;

    const float e   = (float)i * (1.0f / 64.0f);
    const float inv = exp2f(-18.931568569324174f * e);
    const float wavelen = 6.2831853071795865f / inv;
    float f;
    if (wavelen > 8192.0f) {
        f = inv * 0.125f;
    } else if (wavelen < 2048.0f) {
        f = inv;
    } else {
        const float smooth = (8192.0f / wavelen - 1.0f) * (1.0f / 3.0f);
        f = (1.0f - smooth) * 0.125f * inv + smooth * inv;
    }

    float s, c;
    sincosf((float)t * f, &s, &c);

    float* p = q + (size_t)t * (heads * HD) + h * HD;
    const float lo = p[i];
    const float hi = p[i + 64];
    p[i]      = lo * c - hi * s;
    p[i + 64] = hi * c + lo * s;
}

// ---------------------------------------------------------------------------
extern "C" void kernel_launch(void* const* d_in, const int* in_sizes, int n_in,
                              void* d_out, int out_size)
{
    const float* x  = (const float*)d_in[0];
    const float* Wq = (const float*)d_in[1];
    const float* Wk = (const float*)d_in[2];
    const float* Wv = (const float*)d_in[3];
    const float* Wo = (const float*)d_in[4];
    float* out = (float*)d_out;

    float *Q, *K, *VT, *O;
    cudaGetSymbolAddress((void**)&Q,  g_Q);
    cudaGetSymbolAddress((void**)&K,  g_K);
    cudaGetSymbolAddress((void**)&VT, g_VT);
    cudaGetSymbolAddress((void**)&O,  g_O);

    cudaFuncSetAttribute(gemm_tc,    cudaFuncAttributeMaxDynamicSharedMemorySize, GEMM_SMEM);
    cudaFuncSetAttribute(gemm_tc_kv, cudaFuncAttributeMaxDynamicSharedMemorySize, GEMM_SMEM);

    // Q = x * Wq^T  [2048,4096]
    gemm_tc<<<dim3(16, 16), 256, GEMM_SMEM>>>(x, Wq, Q, HID, HID, HID, 4096);
    // K = x * Wk^T and VT = Wv * x^T, fused
    gemm_tc_kv<<<dim3(64, 2), 256, GEMM_SMEM>>>(x, Wk, Wv, K, VT);

    // RoPE in place
    rope_kernel<<<dim3(T_SEQ, NH  / 4), dim3(64, 4)>>>(Q, NH);
    rope_kernel<<<dim3(T_SEQ, NKV / 4), dim3(64, 4)>>>(K, NKV);

    // Fused causal attention
    const int flash_smem = 3 * 128 * FSTR * 4;
    cudaFuncSetAttribute(flash_attn, cudaFuncAttributeMaxDynamicSharedMemorySize, flash_smem);
    flash_attn<<<dim3(16, NH), 256, flash_smem>>>(Q, K, VT, O);

    // out = O * Wo^T  [2048,4096]
    gemm_tc<<<dim3(16, 16), 256, GEMM_SMEM>>>(O, Wo, out, HID, 4096, 4096, HID);
}

// round 7
// speedup vs baseline: 1.7913x; 1.7913x over previous
#include <cuda_runtime.h>
#include <cuda_fp16.h>
#include <math.h>
#include <stdint.h>

#define T_SEQ 2048
#define HID 4096
#define NH 32
#define NKV 8
#define HD 128

// ---------------- scratch (__device__ globals; no allocations) -------------
__device__ float  g_Q  [(size_t)T_SEQ * NH * HD];     // fp32 Q (pre-rope)
__device__ float  g_K  [(size_t)T_SEQ * NKV * HD];    // fp32 K (pre-rope)
__device__ __half g_xh [(size_t)T_SEQ * HID];
__device__ __half g_Wqh[(size_t)NH * HD * HID];
__device__ __half g_Wkh[(size_t)NKV * HD * HID];
__device__ __half g_Wvh[(size_t)NKV * HD * HID];
__device__ __half g_Woh[(size_t)HID * NH * HD];
__device__ __half g_Qh [(size_t)T_SEQ * NH * HD];     // roped, scaled
__device__ __half g_Kh [(size_t)T_SEQ * NKV * HD];    // roped
__device__ __half g_VTh[(size_t)NKV * HD * T_SEQ];    // V^T [h][d][t]
__device__ __half g_Oh [(size_t)T_SEQ * NH * HD];

__device__ __forceinline__ uint32_t smem_u32(const void* p) {
    uint32_t a;
    asm("{ .reg .u64 t; cvta.to.shared.u64 t, %1; cvt.u32.u64 %0, t; }"
        : "=r"(a) : "l"(p));
    return a;
}
__device__ __forceinline__ unsigned h2u(float a, float b) {
    __half2 h = __floats2half2_rn(a, b);
    return *reinterpret_cast<unsigned*>(&h);
}

#define MMA_F16(d, a0,a1,a2,a3, b0,b1)                                        \
    asm volatile(                                                             \
        "mma.sync.aligned.m16n8k16.row.col.f32.f16.f16.f32 "                  \
        "{%0,%1,%2,%3}, {%4,%5,%6,%7}, {%8,%9}, {%0,%1,%2,%3};"               \
        : "+f"((d)[0]), "+f"((d)[1]), "+f"((d)[2]), "+f"((d)[3])              \
        : "r"(a0), "r"(a1), "r"(a2), "r"(a3), "r"(b0), "r"(b1))

#define CP_ASYNC16(dst, src) \
    asm volatile("cp.async.cg.shared.global [%0], [%1], 16;" :: "r"(dst), "l"(src))
#define CP_COMMIT()  asm volatile("cp.async.commit_group;" ::: "memory")
#define CP_WAIT2()   asm volatile("cp.async.wait_group 2;" ::: "memory")
#define CP_WAIT0()   asm volatile("cp.async.wait_group 0;" ::: "memory")

// ---------------------------------------------------------------------------
// fp32 -> fp16 conversion (optionally scaled), vectorized x4
// ---------------------------------------------------------------------------
__global__ void cvt_h(const float* __restrict__ in, __half* __restrict__ out,
                      int n4, float scale)
{
    int i = blockIdx.x * blockDim.x + threadIdx.x;
    if (i < n4) {
        float4 v = reinterpret_cast<const float4*>(in)[i];
        __half2 h0 = __floats2half2_rn(v.x * scale, v.y * scale);
        __half2 h1 = __floats2half2_rn(v.z * scale, v.w * scale);
        reinterpret_cast<__half2*>(out)[2 * i]     = h0;
        reinterpret_cast<__half2*>(out)[2 * i + 1] = h1;
    }
}

// ---------------------------------------------------------------------------
// FP16 GEMM: C[M,N] = A[M,K] * B^T (A [M,K], B [N,K] fp16 row-major).
// Block tile 128x256, K-chunk 32 (2 x k16 steps), 256 threads (8 warps 2x4,
// each 64x64 via m16n8k16, fp32 accum). 3-stage cp.async pipeline.
// smem rows padded to 40 halves (80 B) -> conflict-free fragment LDS.
// Requires M%128==0, N%256==0, K%32==0, K/32>=3.
// ---------------------------------------------------------------------------
#define HSTR 40
#define STG_HALVES ((128 + 256) * HSTR)     // 15360
#define STG_BYTES  (STG_HALVES * 2)         // 30720
#define GEMM_SMEM  (3 * STG_BYTES)          // 92160

__device__ __forceinline__ void gemm_core(
    const __half* __restrict__ A, const __half* __restrict__ B, void* __restrict__ Cv,
    int K, int lda, int ldb, int ldc, int bm, int bn, int half_out)
{
    extern __shared__ __half smh[];
    const uint32_t smb = smem_u32(smh);

    const int tid  = threadIdx.x;
    const int lane = tid & 31;
    const int w    = tid >> 5;
    const int g    = lane >> 2;
    const int t    = lane & 3;
    const int wm   = (w >> 2) * 64;
    const int wn   = (w & 3) * 64;

    float acc[4][8][4];
    #pragma unroll
    for (int mi = 0; mi < 4; mi++)
        #pragma unroll
        for (int ni = 0; ni < 8; ni++)
            #pragma unroll
            for (int q = 0; q < 4; q++) acc[mi][ni][q] = 0.0f;

    // Fill mapping: 16B = 8 halves per cp.async. A: 512 chunks (2/thr), B: 1024 (4/thr).
    const int nch = K >> 5;

    #define GFILL(stage, k0) do {                                              \
        const uint32_t sb = smb + (stage) * STG_BYTES;                          \
        _Pragma("unroll")                                                       \
        for (int p = 0; p < 2; p++) {                                           \
            const int cid = tid + 256 * p;                                      \
            const int r = cid >> 2, c = (cid & 3) * 8;                          \
            CP_ASYNC16(sb + (uint32_t)(r * HSTR + c) * 2u,                      \
                       A + (size_t)(bm + r) * lda + (k0) + c);                  \
        }                                                                       \
        _Pragma("unroll")                                                       \
        for (int p = 0; p < 4; p++) {                                           \
            const int cid = tid + 256 * p;                                      \
            const int r = cid >> 2, c = (cid & 3) * 8;                          \
            CP_ASYNC16(sb + (uint32_t)((128 + r) * HSTR + c) * 2u,              \
                       B + (size_t)(bn + r) * ldb + (k0) + c);                  \
        }                                                                       \
    } while (0)

    GFILL(0, 0);  CP_COMMIT();
    GFILL(1, 32); CP_COMMIT();
    GFILL(2, 64); CP_COMMIT();

    for (int i = 0; i < nch; i++) {
        const int s = i - (i / 3) * 3;
        CP_WAIT2();
        __syncthreads();

        const __half* SA = smh + s * STG_HALVES;
        const __half* SB = SA + 128 * HSTR;

        #pragma unroll
        for (int ks = 0; ks < 2; ks++) {
            const int o = ks * 16;
            unsigned af[4][4], bf[8][2];
            #pragma unroll
            for (int mi = 0; mi < 4; mi++) {
                const int r = wm + mi * 16;
                af[mi][0] = *reinterpret_cast<const unsigned*>(SA + (r + g    ) * HSTR + o + 2 * t    );
                af[mi][1] = *reinterpret_cast<const unsigned*>(SA + (r + g + 8) * HSTR + o + 2 * t    );
                af[mi][2] = *reinterpret_cast<const unsigned*>(SA + (r + g    ) * HSTR + o + 2 * t + 8);
                af[mi][3] = *reinterpret_cast<const unsigned*>(SA + (r + g + 8) * HSTR + o + 2 * t + 8);
            }
            #pragma unroll
            for (int ni = 0; ni < 8; ni++) {
                const int cb = wn + ni * 8 + g;
                bf[ni][0] = *reinterpret_cast<const unsigned*>(SB + cb * HSTR + o + 2 * t    );
                bf[ni][1] = *reinterpret_cast<const unsigned*>(SB + cb * HSTR + o + 2 * t + 8);
            }
            #pragma unroll
            for (int mi = 0; mi < 4; mi++)
                #pragma unroll
                for (int ni = 0; ni < 8; ni++)
                    MMA_F16(acc[mi][ni], af[mi][0], af[mi][1], af[mi][2], af[mi][3],
                            bf[ni][0], bf[ni][1]);
        }
        __syncthreads();

        if (i + 3 < nch) GFILL(s, (i + 3) * 32);
        CP_COMMIT();
    }
    #undef GFILL

    // Epilogue
    if (half_out) {
        __half* C = (__half*)Cv;
        #pragma unroll
        for (int mi = 0; mi < 4; mi++) {
            const size_t r0 = (size_t)(bm + wm + mi * 16 + g) * ldc + bn + wn;
            const size_t r1 = r0 + (size_t)8 * ldc;
            #pragma unroll
            for (int ni = 0; ni < 8; ni++) {
                const int cc = ni * 8 + 2 * t;
                *reinterpret_cast<unsigned*>(C + r0 + cc) = h2u(acc[mi][ni][0], acc[mi][ni][1]);
                *reinterpret_cast<unsigned*>(C + r1 + cc) = h2u(acc[mi][ni][2], acc[mi][ni][3]);
            }
        }
    } else {
        float* C = (float*)Cv;
        #pragma unroll
        for (int mi = 0; mi < 4; mi++) {
            const size_t r0 = (size_t)(bm + wm + mi * 16 + g) * ldc + bn + wn;
            const size_t r1 = r0 + (size_t)8 * ldc;
            #pragma unroll
            for (int ni = 0; ni < 8; ni++) {
                const int cc = ni * 8 + 2 * t;
                *reinterpret_cast<float2*>(C + r0 + cc) = make_float2(acc[mi][ni][0], acc[mi][ni][1]);
                *reinterpret_cast<float2*>(C + r1 + cc) = make_float2(acc[mi][ni][2], acc[mi][ni][3]);
            }
        }
    }
}

__global__ __launch_bounds__(256)
void gemm_h(const __half* __restrict__ A, const __half* __restrict__ B,
            void* __restrict__ C, int K, int lda, int ldb, int ldc, int half_out)
{
    gemm_core(A, B, C, K, lda, ldb, ldc, blockIdx.y * 128, blockIdx.x * 256, half_out);
}

// Fused: K-proj (fp32 out) + VT-proj (fp16 out)
__global__ __launch_bounds__(256)
void gemm_kv(const __half* __restrict__ xh, const __half* __restrict__ Wkh,
             const __half* __restrict__ Wvh, float* __restrict__ K, __half* __restrict__ VT)
{
    if (blockIdx.y == 0)   // K = x*Wk^T [2048,1024]: 16 x 4 tiles
        gemm_core(xh, Wkh, K, HID, HID, HID, NKV * HD,
                  (blockIdx.x >> 2) * 128, (blockIdx.x & 3) * 256, 0);
    else                   // VT = Wv*x^T [1024,2048]: 8 x 8 tiles
        gemm_core(Wvh, xh, VT, HID, HID, HID, T_SEQ,
                  (blockIdx.x >> 3) * 128, (blockIdx.x & 7) * 256, 1);
}

// ---------------------------------------------------------------------------
// Flash attention, fp16 inputs, fp32 online softmax + accumulators.
// One block per (q-block 128 rows, head). 8 warps, warp w owns rows w*16..+15.
// m16n8k16: P accumulator fragments ARE the next A fragments (no shuffles).
// ---------------------------------------------------------------------------
#define FH 136                                  // halves per smem row (272 B)
#define FLASH_SMEM (3 * 128 * FH * 2)           // 104448 B

__global__ __launch_bounds__(256)
void flash_attn(const __half* __restrict__ Qg, const __half* __restrict__ Kg,
                const __half* __restrict__ VTg, __half* __restrict__ Og)
{
    extern __shared__ __half fsm[];
    __half* Qs = fsm;
    __half* Ks = fsm + 128 * FH;
    __half* Vs = fsm + 2 * 128 * FH;
    const uint32_t qb = smem_u32(Qs);
    const uint32_t kb = smem_u32(Ks);
    const uint32_t vb = smem_u32(Vs);

    const int h  = blockIdx.y;
    const int ib = gridDim.x - 1 - blockIdx.x;   // heavy blocks first
    const int kv = h >> 2;
    const int tid  = threadIdx.x;
    const int lane = tid & 31;
    const int w    = tid >> 5;
    const int g    = lane >> 2;
    const int t    = lane & 3;
    const int wr   = w * 16;

    // Q tile prefetch (scale already folded into Qg)
    #pragma unroll
    for (int p = 0; p < 8; p++) {
        const int fidx = tid + 256 * p;
        const int r = fidx >> 4, c = (fidx & 15) * 8;
        CP_ASYNC16(qb + (uint32_t)(r * FH + c) * 2u,
                   Qg + (size_t)(ib * 128 + r) * (NH * HD) + h * HD + c);
    }
    CP_COMMIT();

    float m0 = -1e30f, m1 = -1e30f, l0 = 0.0f, l1 = 0.0f;
    float o[16][4];
    #pragma unroll
    for (int ni = 0; ni < 16; ni++)
        #pragma unroll
        for (int q = 0; q < 4; q++) o[ni][q] = 0.0f;

    for (int j = 0; j <= ib; j++) {
        __syncthreads();   // prior iteration done reading Ks/Vs
        #pragma unroll
        for (int p = 0; p < 8; p++) {
            const int fidx = tid + 256 * p;
            const int r = fidx >> 4, c = (fidx & 15) * 8;
            CP_ASYNC16(kb + (uint32_t)(r * FH + c) * 2u,
                       Kg + (size_t)(j * 128 + r) * (NKV * HD) + kv * HD + c);
            CP_ASYNC16(vb + (uint32_t)(r * FH + c) * 2u,
                       VTg + ((size_t)kv * HD + r) * T_SEQ + j * 128 + c);
        }
        CP_COMMIT();
        CP_WAIT0();
        __syncthreads();

        // S = Q * K^T  (16 x 128 per warp), 8 k16 steps
        float s[16][4];
        #pragma unroll
        for (int ni = 0; ni < 16; ni++)
            #pragma unroll
            for (int q = 0; q < 4; q++) s[ni][q] = 0.0f;

        #pragma unroll
        for (int ks = 0; ks < 8; ks++) {
            const int o16 = ks * 16;
            const unsigned a0 = *reinterpret_cast<const unsigned*>(Qs + (wr + g    ) * FH + o16 + 2 * t    );
            const unsigned a1 = *reinterpret_cast<const unsigned*>(Qs + (wr + g + 8) * FH + o16 + 2 * t    );
            const unsigned a2 = *reinterpret_cast<const unsigned*>(Qs + (wr + g    ) * FH + o16 + 2 * t + 8);
            const unsigned a3 = *reinterpret_cast<const unsigned*>(Qs + (wr + g + 8) * FH + o16 + 2 * t + 8);
            #pragma unroll
            for (int ni = 0; ni < 16; ni++) {
                const unsigned b0 = *reinterpret_cast<const unsigned*>(Ks + (ni * 8 + g) * FH + o16 + 2 * t    );
                const unsigned b1 = *reinterpret_cast<const unsigned*>(Ks + (ni * 8 + g) * FH + o16 + 2 * t + 8);
                MMA_F16(s[ni], a0, a1, a2, a3, b0, b1);
            }
        }

        // Causal mask on the diagonal block
        if (j == ib) {
            #pragma unroll
            for (int ni = 0; ni < 16; ni++) {
                const int c0 = ni * 8 + 2 * t;
                const int r0 = wr + g, r1 = wr + g + 8;
                if (c0     > r0) s[ni][0] = -1e30f;
                if (c0 + 1 > r0) s[ni][1] = -1e30f;
                if (c0     > r1) s[ni][2] = -1e30f;
                if (c0 + 1 > r1) s[ni][3] = -1e30f;
            }
        }

        // Online softmax
        float bm0 = -1e30f, bm1 = -1e30f;
        #pragma unroll
        for (int ni = 0; ni < 16; ni++) {
            bm0 = fmaxf(bm0, fmaxf(s[ni][0], s[ni][1]));
            bm1 = fmaxf(bm1, fmaxf(s[ni][2], s[ni][3]));
        }
        bm0 = fmaxf(bm0, __shfl_xor_sync(0xffffffffu, bm0, 1));
        bm0 = fmaxf(bm0, __shfl_xor_sync(0xffffffffu, bm0, 2));
        bm1 = fmaxf(bm1, __shfl_xor_sync(0xffffffffu, bm1, 1));
        bm1 = fmaxf(bm1, __shfl_xor_sync(0xffffffffu, bm1, 2));

        const float mn0 = fmaxf(m0, bm0), mn1 = fmaxf(m1, bm1);
        const float al0 = __expf(m0 - mn0), al1 = __expf(m1 - mn1);
        m0 = mn0; m1 = mn1;

        float rs0 = 0.0f, rs1 = 0.0f;
        #pragma unroll
        for (int ni = 0; ni < 16; ni++) {
            s[ni][0] = __expf(s[ni][0] - mn0);
            s[ni][1] = __expf(s[ni][1] - mn0);
            s[ni][2] = __expf(s[ni][2] - mn1);
            s[ni][3] = __expf(s[ni][3] - mn1);
            rs0 += s[ni][0] + s[ni][1];
            rs1 += s[ni][2] + s[ni][3];
        }
        rs0 += __shfl_xor_sync(0xffffffffu, rs0, 1);
        rs0 += __shfl_xor_sync(0xffffffffu, rs0, 2);
        rs1 += __shfl_xor_sync(0xffffffffu, rs1, 1);
        rs1 += __shfl_xor_sync(0xffffffffu, rs1, 2);
        l0 = l0 * al0 + rs0;
        l1 = l1 * al1 + rs1;

        #pragma unroll
        for (int ni = 0; ni < 16; ni++) {
            o[ni][0] *= al0; o[ni][1] *= al0;
            o[ni][2] *= al1; o[ni][3] *= al1;
        }

        // O += P * V : P C-fragments map directly onto fp16 A-fragments
        #pragma unroll
        for (int kt = 0; kt < 8; kt++) {
            const unsigned a0 = h2u(s[2 * kt    ][0], s[2 * kt    ][1]);
            const unsigned a1 = h2u(s[2 * kt    ][2], s[2 * kt    ][3]);
            const unsigned a2 = h2u(s[2 * kt + 1][0], s[2 * kt + 1][1]);
            const unsigned a3 = h2u(s[2 * kt + 1][2], s[2 * kt + 1][3]);
            const int o16 = kt * 16;
            #pragma unroll
            for (int ni = 0; ni < 16; ni++) {
                const unsigned b0 = *reinterpret_cast<const unsigned*>(Vs + (ni * 8 + g) * FH + o16 + 2 * t    );
                const unsigned b1 = *reinterpret_cast<const unsigned*>(Vs + (ni * 8 + g) * FH + o16 + 2 * t + 8);
                MMA_F16(o[ni], a0, a1, a2, a3, b0, b1);
            }
        }
    }

    // Epilogue: normalize and store fp16
    const float i0 = 1.0f / l0, i1 = 1.0f / l1;
    const size_t r0 = (size_t)(ib * 128 + wr + g) * (NH * HD) + h * HD;
    const size_t r1 = r0 + (size_t)8 * (NH * HD);
    #pragma unroll
    for (int ni = 0; ni < 16; ni++) {
        const int cc = ni * 8 + 2 * t;
        *reinterpret_cast<unsigned*>(Og + r0 + cc) = h2u(o[ni][0] * i0, o[ni][1] * i0);
        *reinterpret_cast<unsigned*>(Og + r1 + cc) = h2u(o[ni][2] * i1, o[ni][3] * i1);
    }
}

// ---------------------------------------------------------------------------
// Llama-3 RoPE in place on fp32 [T, heads*128] (unchanged from R4)
// ---------------------------------------------------------------------------
__global__ void rope_kernel(float* __restrict__ q, int heads)
{
    const int t = blockIdx.x;
    const int h = blockIdx.y * 4 + threadIdx.y;
    const int i = threadIdx.x;

    const float e   = (float)i * (1.0f / 64.0f);
    const float inv = exp2f(-18.931568569324174f * e);
    const float wavelen = 6.2831853071795865f / inv;
    float f;
    if (wavelen > 8192.0f) {
        f = inv * 0.125f;
    } else if (wavelen < 2048.0f) {
        f = inv;
    } else {
        const float smooth = (8192.0f / wavelen - 1.0f) * (1.0f / 3.0f);
        f = (1.0f - smooth) * 0.125f * inv + smooth * inv;
    }

    float s, c;
    sincosf((float)t * f, &s, &c);

    float* p = q + (size_t)t * (heads * HD) + h * HD;
    const float lo = p[i];
    const float hi = p[i + 64];
    p[i]      = lo * c - hi * s;
    p[i + 64] = hi * c + lo * s;
}

// ---------------------------------------------------------------------------
extern "C" void kernel_launch(void* const* d_in, const int* in_sizes, int n_in,
                              void* d_out, int out_size)
{
    const float* x  = (const float*)d_in[0];
    const float* Wq = (const float*)d_in[1];
    const float* Wk = (const float*)d_in[2];
    const float* Wv = (const float*)d_in[3];
    const float* Wo = (const float*)d_in[4];
    float* out = (float*)d_out;

    float *Q, *K;
    __half *xh, *Wqh, *Wkh, *Wvh, *Woh, *Qh, *Kh, *VTh, *Oh;
    cudaGetSymbolAddress((void**)&Q,   g_Q);
    cudaGetSymbolAddress((void**)&K,   g_K);
    cudaGetSymbolAddress((void**)&xh,  g_xh);
    cudaGetSymbolAddress((void**)&Wqh, g_Wqh);
    cudaGetSymbolAddress((void**)&Wkh, g_Wkh);
    cudaGetSymbolAddress((void**)&Wvh, g_Wvh);
    cudaGetSymbolAddress((void**)&Woh, g_Woh);
    cudaGetSymbolAddress((void**)&Qh,  g_Qh);
    cudaGetSymbolAddress((void**)&Kh,  g_Kh);
    cudaGetSymbolAddress((void**)&VTh, g_VTh);
    cudaGetSymbolAddress((void**)&Oh,  g_Oh);

    // Convert inputs to fp16
    cvt_h<<< (T_SEQ * HID / 4 + 255) / 256, 256>>>(x,  xh,  T_SEQ * HID / 4, 1.0f);
    cvt_h<<< (NH * HD * HID / 4 + 255) / 256, 256>>>(Wq, Wqh, NH * HD * HID / 4, 1.0f);
    cvt_h<<< (NKV * HD * HID / 4 + 255) / 256, 256>>>(Wk, Wkh, NKV * HD * HID / 4, 1.0f);
    cvt_h<<< (NKV * HD * HID / 4 + 255) / 256, 256>>>(Wv, Wvh, NKV * HD * HID / 4, 1.0f);
    cvt_h<<< (HID * NH * HD / 4 + 255) / 256, 256>>>(Wo, Woh, HID * NH * HD / 4, 1.0f);

    cudaFuncSetAttribute(gemm_h,  cudaFuncAttributeMaxDynamicSharedMemorySize, GEMM_SMEM);
    cudaFuncSetAttribute(gemm_kv, cudaFuncAttributeMaxDynamicSharedMemorySize, GEMM_SMEM);
    cudaFuncSetAttribute(flash_attn, cudaFuncAttributeMaxDynamicSharedMemorySize, FLASH_SMEM);

    // Q = x*Wq^T (fp32 out, rope wants fp32)
    gemm_h<<<dim3(16, 16), 256, GEMM_SMEM>>>(xh, Wqh, Q, HID, HID, HID, 4096, 0);
    // K = x*Wk^T (fp32) and VT = Wv*x^T (fp16), fused
    gemm_kv<<<dim3(64, 2), 256, GEMM_SMEM>>>(xh, Wkh, Wvh, K, VTh);

    // RoPE in fp32 (single-rounding discipline)
    rope_kernel<<<dim3(T_SEQ, NH  / 4), dim3(64, 4)>>>(Q, NH);
    rope_kernel<<<dim3(T_SEQ, NKV / 4), dim3(64, 4)>>>(K, NKV);

    // Q -> fp16 with 1/sqrt(128) folded; K -> fp16
    cvt_h<<< (T_SEQ * NH * HD / 4 + 255) / 256, 256>>>(Q, Qh, T_SEQ * NH * HD / 4,
                                                       0.088388347648318447f);
    cvt_h<<< (T_SEQ * NKV * HD / 4 + 255) / 256, 256>>>(K, Kh, T_SEQ * NKV * HD / 4, 1.0f);

    // Fused causal attention
    flash_attn<<<dim3(16, NH), 256, FLASH_SMEM>>>(Qh, Kh, VTh, Oh);

    // out = O*Wo^T (fp32 out)
    gemm_h<<<dim3(16, 16), 256, GEMM_SMEM>>>(Oh, Woh, out, 4096, 4096, 4096, HID, 0);
}